// round 4
// baseline (speedup 1.0000x reference)
#include <cuda_runtime.h>

// LSTM T=512, B=4096, I=10, H=20. One WARP per batch row, warp-private state,
// __syncwarp-only. 96 padded gate-rows (4 gates x 24), 3 per lane, weights in
// registers as f32x2; fma.rn.f32x2 packed math; tanh.approx for activations.
// R4 changes vs R3: full-grid residency (launch_bounds(128,12): 1024 CTAs fit
// in ONE wave) + x[t+1] register prefetch off the critical path.

#define T_STEPS 512
#define BATCH   4096
#define ISZ     10
#define HSZ     20
#define JPAD    24
#define WARPS_PER_CTA 4
#define NTHREADS (WARPS_PER_CTA * 32)

typedef unsigned long long u64;

__device__ __forceinline__ u64 pack2(float x, float y) {
    u64 r; asm("mov.b64 %0, {%1,%2};" : "=l"(r) : "f"(x), "f"(y)); return r;
}
__device__ __forceinline__ void unpack2(u64 v, float& x, float& y) {
    asm("mov.b64 {%0,%1}, %2;" : "=f"(x), "=f"(y) : "l"(v));
}
__device__ __forceinline__ u64 ffma2(u64 a, u64 b, u64 c) {
    u64 r; asm("fma.rn.f32x2 %0, %1, %2, %3;" : "=l"(r) : "l"(a), "l"(b), "l"(c));
    return r;
}
__device__ __forceinline__ float tanh_fast(float x) {
    float y; asm("tanh.approx.f32 %0, %1;" : "=f"(y) : "f"(x)); return y;
}

#define WREG_F (2 * JPAD + 4 * JPAD)   // h double buffer + activated gates

__global__ void __launch_bounds__(NTHREADS, 12) lstm_warp_kernel(
    const float* __restrict__ x,      // [T, B, I]
    const float* __restrict__ h0,     // [B, H]
    const float* __restrict__ c0,     // [B, H]
    const float* __restrict__ Wih,    // [4H, I]
    const float* __restrict__ Whh,    // [4H, H]
    const float* __restrict__ bih,    // [4H]
    const float* __restrict__ bhh,    // [4H]
    float* __restrict__ out,
    long long out_size)
{
    const int lane = threadIdx.x & 31;
    const int w    = threadIdx.x >> 5;
    const int b    = blockIdx.x * WARPS_PER_CTA + w;

    __shared__ __align__(16) float sm[WARPS_PER_CTA][WREG_F];
    float* const hbuf = &sm[w][0];          // [2][JPAD]
    float* const gbuf = &sm[w][2 * JPAD];   // [96] activated gates

    // ---- per-lane weights: 3 padded gate-rows r = 3*lane + rr ----
    u64 wih2[3][ISZ / 2];
    u64 whh2[3][HSZ / 2];
    u64 bias2[3];
    float s_[3], o_[3];
#pragma unroll
    for (int rr = 0; rr < 3; rr++) {
        const int r  = 3 * lane + rr;
        const int g  = r / JPAD;
        const int jj = r - g * JPAD;
        const bool valid = (jj < HSZ);
        const int row = g * HSZ + jj;
        if (valid) {
            const float* wr = Wih + row * ISZ;
#pragma unroll
            for (int k = 0; k < ISZ / 2; k++)
                wih2[rr][k] = *reinterpret_cast<const u64*>(wr + 2 * k);
            const float* wr2 = Whh + row * HSZ;
#pragma unroll
            for (int k = 0; k < HSZ / 2; k++)
                whh2[rr][k] = *reinterpret_cast<const u64*>(wr2 + 2 * k);
            bias2[rr] = pack2(bih[row] + bhh[row], 0.0f);
        } else {
#pragma unroll
            for (int k = 0; k < ISZ / 2; k++) wih2[rr][k] = 0ull;
#pragma unroll
            for (int k = 0; k < HSZ / 2; k++) whh2[rr][k] = 0ull;
            bias2[rr] = 0ull;
        }
        // act(x) = fma(tanh(s*x), s, 1-s): s=1 -> tanh (gate g), s=0.5 -> sigmoid
        s_[rr] = (g == 2) ? 1.0f : 0.5f;
        o_[rr] = 1.0f - s_[rr];
    }

    float c = 0.0f, hn = 0.0f;
    if (lane < HSZ) {
        c = c0[(size_t)b * HSZ + lane];
        hbuf[lane] = h0[(size_t)b * HSZ + lane];
    }
    __syncwarp();

    const float* xp = x + (size_t)b * ISZ;
    float*       op = out + (size_t)b * HSZ;
    const size_t x_step = (size_t)BATCH * ISZ;
    const size_t o_step = (size_t)BATCH * HSZ;

    // prefetch x[0]
    u64 xc[ISZ / 2];
#pragma unroll
    for (int k = 0; k < ISZ / 2; k++)
        xc[k] = *reinterpret_cast<const u64*>(xp + 2 * k);

    for (int t = 0; t < T_STEPS; t++) {
        float* const hcur = hbuf + (t & 1) * JPAD;
        float* const hnxt = hbuf + ((t & 1) ^ 1) * JPAD;

        // issue x[t+1] loads NOW; consumed next iteration
        u64 xn[ISZ / 2];
        {
            const float* xq = (t + 1 < T_STEPS) ? xp + x_step : xp;
#pragma unroll
            for (int k = 0; k < ISZ / 2; k++)
                xn[k] = *reinterpret_cast<const u64*>(xq + 2 * k);
        }

        // ---- phase 1: 32 lanes accumulate + activate 3 gate-rows each ----
        u64 a0 = bias2[0], a1 = bias2[1], a2 = bias2[2];

#pragma unroll
        for (int k = 0; k < ISZ / 2; k++) {
            a0 = ffma2(wih2[0][k], xc[k], a0);
            a1 = ffma2(wih2[1][k], xc[k], a1);
            a2 = ffma2(wih2[2][k], xc[k], a2);
        }

#pragma unroll
        for (int k4 = 0; k4 < HSZ / 4; k4++) {
            const ulonglong2 hv = *reinterpret_cast<const ulonglong2*>(hcur + 4 * k4);
            a0 = ffma2(whh2[0][2 * k4], hv.x, a0);
            a1 = ffma2(whh2[1][2 * k4], hv.x, a1);
            a2 = ffma2(whh2[2][2 * k4], hv.x, a2);
            a0 = ffma2(whh2[0][2 * k4 + 1], hv.y, a0);
            a1 = ffma2(whh2[1][2 * k4 + 1], hv.y, a1);
            a2 = ffma2(whh2[2][2 * k4 + 1], hv.y, a2);
        }

        float lo, hi;
        unpack2(a0, lo, hi);
        const float v0 = fmaf(tanh_fast(s_[0] * (lo + hi)), s_[0], o_[0]);
        unpack2(a1, lo, hi);
        const float v1 = fmaf(tanh_fast(s_[1] * (lo + hi)), s_[1], o_[1]);
        unpack2(a2, lo, hi);
        const float v2 = fmaf(tanh_fast(s_[2] * (lo + hi)), s_[2], o_[2]);

        gbuf[3 * lane + 0] = v0;
        gbuf[3 * lane + 1] = v1;
        gbuf[3 * lane + 2] = v2;
        __syncwarp();

        // ---- phase 2: lanes 0..19 update c, h ----
        if (lane < HSZ) {
            const float gi = gbuf[lane];
            const float gf = gbuf[JPAD + lane];
            const float gg = gbuf[2 * JPAD + lane];
            const float go = gbuf[3 * JPAD + lane];
            c  = fmaf(gf, c, gi * gg);
            hn = go * tanh_fast(c);
            hnxt[lane] = hn;
            op[lane]   = hn;
        }
        __syncwarp();

#pragma unroll
        for (int k = 0; k < ISZ / 2; k++) xc[k] = xn[k];

        xp += x_step;
        op += o_step;
    }

    const long long base = (long long)T_STEPS * BATCH * HSZ;
    if (lane < HSZ && out_size >= base + 2LL * BATCH * HSZ) {
        out[base + (size_t)b * HSZ + lane] = hn;
        out[base + (size_t)BATCH * HSZ + (size_t)b * HSZ + lane] = c;
    }
}

extern "C" void kernel_launch(void* const* d_in, const int* in_sizes, int n_in,
                              void* d_out, int out_size) {
    const float* x   = (const float*)d_in[0];
    const float* h0  = (const float*)d_in[1];
    const float* c0  = (const float*)d_in[2];
    const float* Wih = (const float*)d_in[3];
    const float* Whh = (const float*)d_in[4];
    const float* bih = (const float*)d_in[5];
    const float* bhh = (const float*)d_in[6];
    float* out = (float*)d_out;

    dim3 grid(BATCH / WARPS_PER_CTA);   // 1024 CTAs — one resident wave
    dim3 block(NTHREADS);               // 128 threads
    lstm_warp_kernel<<<grid, block>>>(x, h0, c0, Wih, Whh, bih, bhh,
                                      out, (long long)out_size);
}

// round 5
// speedup vs baseline: 4.8779x; 4.8779x over previous
#include <cuda_runtime.h>

// LSTM T=512, B=4096, I=10, H=20. One warp per TWO batch rows (weights
// register-resident once, amortized over 2 rows -> 512 CTAs = ONE wave at
// 4 CTA/SM, 128 regs). Warp-private state, __syncwarp only. 96 padded
// gate-rows (4 gates x 24), 3 per lane; fma.rn.f32x2; tanh.approx.
// x[t+1] staged gmem->reg->smem per warp, hidden under the step.

#define T_STEPS 512
#define BATCH   4096
#define ISZ     10
#define HSZ     20
#define JPAD    24
#define ROWS_PER_WARP 2
#define WARPS_PER_CTA 4
#define NB       (WARPS_PER_CTA * ROWS_PER_WARP)   // 8 rows per CTA
#define NTHREADS (WARPS_PER_CTA * 32)

typedef unsigned long long u64;

__device__ __forceinline__ u64 pack2(float x, float y) {
    u64 r; asm("mov.b64 %0, {%1,%2};" : "=l"(r) : "f"(x), "f"(y)); return r;
}
__device__ __forceinline__ void unpack2(u64 v, float& x, float& y) {
    asm("mov.b64 {%0,%1}, %2;" : "=f"(x), "=f"(y) : "l"(v));
}
__device__ __forceinline__ u64 ffma2(u64 a, u64 b, u64 c) {
    u64 r; asm("fma.rn.f32x2 %0, %1, %2, %3;" : "=l"(r) : "l"(a), "l"(b), "l"(c));
    return r;
}
__device__ __forceinline__ float tanh_fast(float x) {
    float y; asm("tanh.approx.f32 %0, %1;" : "=f"(y) : "f"(x)); return y;
}

// per-warp smem floats:
//   hbuf: 2 rows x 2 bufs x JPAD          = 96
//   gbuf: 2 rows x 4*JPAD                 = 192
//   xs:   2 bufs x 2 rows x 12 (40B+pad)  = 48
#define H_OFF   0
#define G_OFF   96
#define X_OFF   (96 + 192)
#define WREG_F  (96 + 192 + 48)

__global__ void __launch_bounds__(NTHREADS, 4) lstm_warp2_kernel(
    const float* __restrict__ x,      // [T, B, I]
    const float* __restrict__ h0,     // [B, H]
    const float* __restrict__ c0,     // [B, H]
    const float* __restrict__ Wih,    // [4H, I]
    const float* __restrict__ Whh,    // [4H, H]
    const float* __restrict__ bih,    // [4H]
    const float* __restrict__ bhh,    // [4H]
    float* __restrict__ out,
    long long out_size)
{
    const int lane = threadIdx.x & 31;
    const int w    = threadIdx.x >> 5;
    const int b0   = blockIdx.x * NB + 2 * w;     // this warp's rows: b0, b0+1

    __shared__ __align__(16) float sm[WARPS_PER_CTA][WREG_F];
    float* const hbuf = &sm[w][H_OFF];   // [row][buf][JPAD]
    float* const gbuf = &sm[w][G_OFF];   // [row][4*JPAD]
    float* const xs   = &sm[w][X_OFF];   // [buf][row][12]

    // ---- per-lane weights: 3 padded gate-rows r = 3*lane + rr ----
    u64 wih2[3][ISZ / 2];
    u64 whh2[3][HSZ / 2];
    u64 bias2[3];
    float s_[3], o_[3];
#pragma unroll
    for (int rr = 0; rr < 3; rr++) {
        const int r  = 3 * lane + rr;
        const int g  = r / JPAD;
        const int jj = r - g * JPAD;
        const int row = g * HSZ + jj;
        if (jj < HSZ) {
            const float* wr = Wih + row * ISZ;
#pragma unroll
            for (int k = 0; k < ISZ / 2; k++)
                wih2[rr][k] = *reinterpret_cast<const u64*>(wr + 2 * k);
            const float* wr2 = Whh + row * HSZ;
#pragma unroll
            for (int k = 0; k < HSZ / 2; k++)
                whh2[rr][k] = *reinterpret_cast<const u64*>(wr2 + 2 * k);
            bias2[rr] = pack2(bih[row] + bhh[row], 0.0f);
        } else {
#pragma unroll
            for (int k = 0; k < ISZ / 2; k++) wih2[rr][k] = 0ull;
#pragma unroll
            for (int k = 0; k < HSZ / 2; k++) whh2[rr][k] = 0ull;
            bias2[rr] = 0ull;
        }
        s_[rr] = (g == 2) ? 1.0f : 0.5f;   // act = fma(tanh(s*z), s, 1-s)
        o_[rr] = 1.0f - s_[rr];
    }

    // ---- init state: lanes 0-19 own unit j=lane for both rows ----
    float c0r[ROWS_PER_WARP] = {0.f, 0.f};
    float hnr[ROWS_PER_WARP] = {0.f, 0.f};
    if (lane < HSZ) {
#pragma unroll
        for (int r = 0; r < ROWS_PER_WARP; r++) {
            c0r[r] = c0[(size_t)(b0 + r) * HSZ + lane];
            hbuf[r * 2 * JPAD + lane] = h0[(size_t)(b0 + r) * HSZ + lane];
        }
    }

    // stage x[0]: warp's 80B chunk is contiguous at x + b0*ISZ
    const float* xbase = x + (size_t)b0 * ISZ;
    const size_t x_step = (size_t)BATCH * ISZ;
    if (lane < 10) {
        const u64 v = *reinterpret_cast<const u64*>(xbase + 2 * lane);
        const int so = (lane < 5) ? 2 * lane : 12 + 2 * (lane - 5);
        *reinterpret_cast<u64*>(xs + so) = v;
    }
    __syncwarp();

    float* op = out + (size_t)b0 * HSZ;
    const size_t o_step = (size_t)BATCH * HSZ;

    for (int t = 0; t < T_STEPS; t++) {
        const int cur = t & 1;

        // issue x[t+1] LDG now; STS at end of step (full-step cover)
        u64 xpre = 0ull;
        if (lane < 10) {
            const float* xq = xbase + (size_t)((t + 1 < T_STEPS) ? t + 1 : t) * x_step;
            xpre = *reinterpret_cast<const u64*>(xq + 2 * lane);
        }

        // ---- phase 1: 6 accumulators (3 gate-rows x 2 batch rows) ----
        u64 acc[ROWS_PER_WARP][3];
#pragma unroll
        for (int r = 0; r < ROWS_PER_WARP; r++) {
            acc[r][0] = bias2[0]; acc[r][1] = bias2[1]; acc[r][2] = bias2[2];
        }

        // x projection from staged smem (broadcast LDS)
#pragma unroll
        for (int r = 0; r < ROWS_PER_WARP; r++) {
            const float* xrow = xs + cur * 24 + r * 12;
            const ulonglong2 xa = *reinterpret_cast<const ulonglong2*>(xrow);
            const ulonglong2 xb2 = *reinterpret_cast<const ulonglong2*>(xrow + 4);
            const u64 xc2 = *reinterpret_cast<const u64*>(xrow + 8);
            acc[r][0] = ffma2(wih2[0][0], xa.x, acc[r][0]);
            acc[r][1] = ffma2(wih2[1][0], xa.x, acc[r][1]);
            acc[r][2] = ffma2(wih2[2][0], xa.x, acc[r][2]);
            acc[r][0] = ffma2(wih2[0][1], xa.y, acc[r][0]);
            acc[r][1] = ffma2(wih2[1][1], xa.y, acc[r][1]);
            acc[r][2] = ffma2(wih2[2][1], xa.y, acc[r][2]);
            acc[r][0] = ffma2(wih2[0][2], xb2.x, acc[r][0]);
            acc[r][1] = ffma2(wih2[1][2], xb2.x, acc[r][1]);
            acc[r][2] = ffma2(wih2[2][2], xb2.x, acc[r][2]);
            acc[r][0] = ffma2(wih2[0][3], xb2.y, acc[r][0]);
            acc[r][1] = ffma2(wih2[1][3], xb2.y, acc[r][1]);
            acc[r][2] = ffma2(wih2[2][3], xb2.y, acc[r][2]);
            acc[r][0] = ffma2(wih2[0][4], xc2, acc[r][0]);
            acc[r][1] = ffma2(wih2[1][4], xc2, acc[r][1]);
            acc[r][2] = ffma2(wih2[2][4], xc2, acc[r][2]);
        }

        // recurrent projection
#pragma unroll
        for (int r = 0; r < ROWS_PER_WARP; r++) {
            const float* hcur = hbuf + r * 2 * JPAD + cur * JPAD;
#pragma unroll
            for (int k4 = 0; k4 < HSZ / 4; k4++) {
                const ulonglong2 hv = *reinterpret_cast<const ulonglong2*>(hcur + 4 * k4);
                acc[r][0] = ffma2(whh2[0][2 * k4], hv.x, acc[r][0]);
                acc[r][1] = ffma2(whh2[1][2 * k4], hv.x, acc[r][1]);
                acc[r][2] = ffma2(whh2[2][2 * k4], hv.x, acc[r][2]);
                acc[r][0] = ffma2(whh2[0][2 * k4 + 1], hv.y, acc[r][0]);
                acc[r][1] = ffma2(whh2[1][2 * k4 + 1], hv.y, acc[r][1]);
                acc[r][2] = ffma2(whh2[2][2 * k4 + 1], hv.y, acc[r][2]);
            }
        }

        // activations + gate store (stride-3 conflict-free)
#pragma unroll
        for (int r = 0; r < ROWS_PER_WARP; r++) {
            float lo, hi;
            unpack2(acc[r][0], lo, hi);
            const float v0 = fmaf(tanh_fast(s_[0] * (lo + hi)), s_[0], o_[0]);
            unpack2(acc[r][1], lo, hi);
            const float v1 = fmaf(tanh_fast(s_[1] * (lo + hi)), s_[1], o_[1]);
            unpack2(acc[r][2], lo, hi);
            const float v2 = fmaf(tanh_fast(s_[2] * (lo + hi)), s_[2], o_[2]);
            float* gb = gbuf + r * 4 * JPAD;
            gb[3 * lane + 0] = v0;
            gb[3 * lane + 1] = v1;
            gb[3 * lane + 2] = v2;
        }
        __syncwarp();

        // ---- phase 2: lanes 0..19 update c, h for both rows ----
        if (lane < HSZ) {
#pragma unroll
            for (int r = 0; r < ROWS_PER_WARP; r++) {
                const float* gb = gbuf + r * 4 * JPAD;
                const float gi = gb[lane];
                const float gf = gb[JPAD + lane];
                const float gg = gb[2 * JPAD + lane];
                const float go = gb[3 * JPAD + lane];
                c0r[r] = fmaf(gf, c0r[r], gi * gg);
                hnr[r] = go * tanh_fast(c0r[r]);
                hbuf[r * 2 * JPAD + (cur ^ 1) * JPAD + lane] = hnr[r];
                op[(size_t)r * HSZ + lane] = hnr[r];
            }
        }

        // stage x[t+1] into the other buffer, then one sync covers everything
        if (lane < 10) {
            const int so = (cur ^ 1) * 24 + ((lane < 5) ? 2 * lane : 12 + 2 * (lane - 5));
            *reinterpret_cast<u64*>(xs + so) = xpre;
        }
        __syncwarp();

        op += o_step;
    }

    // ---- final h, c appended after outputs ----
    const long long base = (long long)T_STEPS * BATCH * HSZ;
    if (lane < HSZ && out_size >= base + 2LL * BATCH * HSZ) {
#pragma unroll
        for (int r = 0; r < ROWS_PER_WARP; r++) {
            out[base + (size_t)(b0 + r) * HSZ + lane] = hnr[r];
            out[base + (size_t)BATCH * HSZ + (size_t)(b0 + r) * HSZ + lane] = c0r[r];
        }
    }
}

extern "C" void kernel_launch(void* const* d_in, const int* in_sizes, int n_in,
                              void* d_out, int out_size) {
    const float* x   = (const float*)d_in[0];
    const float* h0  = (const float*)d_in[1];
    const float* c0  = (const float*)d_in[2];
    const float* Wih = (const float*)d_in[3];
    const float* Whh = (const float*)d_in[4];
    const float* bih = (const float*)d_in[5];
    const float* bhh = (const float*)d_in[6];
    float* out = (float*)d_out;

    dim3 grid(BATCH / NB);     // 512 CTAs -> one resident wave at 4 CTA/SM
    dim3 block(NTHREADS);      // 128 threads
    lstm_warp2_kernel<<<grid, block>>>(x, h0, c0, Wih, Whh, bih, bhh,
                                       out, (long long)out_size);
}